// round 2
// baseline (speedup 1.0000x reference)
#include <cuda_runtime.h>
#include <cstdint>
#include <cstddef>

// out = relu(x[131072,256] @ W[256,256]^T + b[256]), fp32 in/out.
// Portable-PTX tensor path (ptxas target is sm_103 WITHOUT the 'a' feature set,
// so no tcgen05/TMA): mma.sync.m16n8k8 tf32 + cp.async double buffering.
// W is pre-converted (round-to-nearest) to tf32 once into __device__ scratch;
// x is converted on the fragment-load path.

#define DEVI __device__ __forceinline__

static constexpr int M_TOTAL = 131072;
static constexpr int N = 256;
static constexpr int K = 256;
static constexpr int BM = 64;          // M rows per CTA
static constexpr int KC = 32;          // K chunk per pipeline stage
static constexpr int PAD = 36;         // smem row stride in floats (conflict-free)
static constexpr int A_STAGE = BM * PAD * 4;    // 9216 B
static constexpr int B_STAGE = N  * PAD * 4;    // 36864 B
static constexpr int STAGE   = A_STAGE + B_STAGE;
static constexpr int SM_TILES = 1024;  // [0,1024) = bias
static constexpr int SMEM_TOTAL = SM_TILES + 2 * STAGE;  // 93184 B

__device__ uint32_t g_wtf32[N * K];    // W pre-rounded to tf32 bit patterns

DEVI uint32_t smem_u32(const void* p) {
    uint32_t a;
    asm("{ .reg .u64 t; cvta.to.shared.u64 t, %1; cvt.u32.u64 %0, t; }"
        : "=r"(a) : "l"(p));
    return a;
}

DEVI uint32_t f2tf32(float f) {
    uint32_t r;
    asm("cvt.rna.tf32.f32 %0, %1;" : "=r"(r) : "f"(f));
    return r;
}

DEVI void cp16(uint32_t dst, const void* src) {
    asm volatile("cp.async.cg.shared.global [%0], [%1], 16;"
                 :: "r"(dst), "l"(__cvta_generic_to_global(src)) : "memory");
}

DEVI void mma_tf32(float* c, const uint32_t* a, const uint32_t* b) {
    asm volatile(
        "mma.sync.aligned.m16n8k8.row.col.f32.tf32.tf32.f32 "
        "{%0,%1,%2,%3}, {%4,%5,%6,%7}, {%8,%9}, {%0,%1,%2,%3};"
        : "+f"(c[0]), "+f"(c[1]), "+f"(c[2]), "+f"(c[3])
        : "r"(a[0]), "r"(a[1]), "r"(a[2]), "r"(a[3]), "r"(b[0]), "r"(b[1]));
}

__global__ void convert_w_kernel(const float* __restrict__ W) {
    int i = blockIdx.x * blockDim.x + threadIdx.x;   // 16384 threads
    #pragma unroll
    for (int j = 0; j < 4; ++j) {
        int idx = i + j * 16384;
        g_wtf32[idx] = f2tf32(W[idx]);
    }
}

__global__ void __launch_bounds__(256)
gemm_tf32_kernel(const float* __restrict__ x,
                 const float* __restrict__ bias,
                 float* __restrict__ out) {
    extern __shared__ char smem[];
    float* sbias = reinterpret_cast<float*>(smem);
    const uint32_t sbase = smem_u32(smem);
    const int tid = threadIdx.x;
    const int lane = tid & 31;
    const int wid = tid >> 5;
    const int warp_m = wid & 1;        // 2 warps in M
    const int warp_n = wid >> 1;       // 4 warps in N
    const int m_base = blockIdx.x * BM;

    sbias[tid] = bias[tid];

    const int gid = lane >> 2;         // group id 0..7
    const int tg  = lane & 3;          // thread-in-group 0..3

    float acc[2][8][4];
    #pragma unroll
    for (int mt = 0; mt < 2; ++mt)
        #pragma unroll
        for (int nt = 0; nt < 8; ++nt)
            #pragma unroll
            for (int j = 0; j < 4; ++j)
                acc[mt][nt][j] = 0.0f;

    // ---- cp.async chunk loader: A(64xKC fp32 from x) + B(256xKC tf32 bits) ----
    auto load_chunk = [&](int kt, int s) {
        uint32_t dA = sbase + SM_TILES + s * STAGE;
        uint32_t dB = dA + A_STAGE;
        const float* srcA = x + (size_t)m_base * K + kt * KC;
        const uint32_t* srcB = g_wtf32 + kt * KC;
        #pragma unroll
        for (int i = 0; i < 2; ++i) {                 // 512 16B granules of A
            int g = tid + i * 256;
            int row = g >> 3, ch = g & 7;
            cp16(dA + row * (PAD * 4) + ch * 16, srcA + (size_t)row * K + ch * 4);
        }
        #pragma unroll
        for (int i = 0; i < 8; ++i) {                 // 2048 16B granules of B
            int g = tid + i * 256;
            int row = g >> 3, ch = g & 7;
            cp16(dB + row * (PAD * 4) + ch * 16, srcB + (size_t)row * K + ch * 4);
        }
        asm volatile("cp.async.commit_group;" ::: "memory");
    };

    load_chunk(0, 0);
    load_chunk(1, 1);

    #pragma unroll 1
    for (int kt = 0; kt < 8; ++kt) {
        if (kt < 7)
            asm volatile("cp.async.wait_group 1;" ::: "memory");
        else
            asm volatile("cp.async.wait_group 0;" ::: "memory");
        __syncthreads();

        const int s = kt & 1;
        const float*    A  = reinterpret_cast<const float*>(smem + SM_TILES + s * STAGE);
        const uint32_t* Bp = reinterpret_cast<const uint32_t*>(smem + SM_TILES + s * STAGE + A_STAGE);

        #pragma unroll
        for (int ks = 0; ks < 4; ++ks) {
            const int koff = ks * 8 + tg;
            uint32_t a[2][4];
            #pragma unroll
            for (int mt = 0; mt < 2; ++mt) {
                int r = warp_m * 32 + mt * 16 + gid;
                a[mt][0] = f2tf32(A[r * PAD + koff]);
                a[mt][1] = f2tf32(A[(r + 8) * PAD + koff]);
                a[mt][2] = f2tf32(A[r * PAD + koff + 4]);
                a[mt][3] = f2tf32(A[(r + 8) * PAD + koff + 4]);
            }
            uint32_t b[8][2];
            #pragma unroll
            for (int nt = 0; nt < 8; ++nt) {
                int n = warp_n * 64 + nt * 8 + gid;
                b[nt][0] = Bp[n * PAD + koff];
                b[nt][1] = Bp[n * PAD + koff + 4];
            }
            #pragma unroll
            for (int mt = 0; mt < 2; ++mt)
                #pragma unroll
                for (int nt = 0; nt < 8; ++nt)
                    mma_tf32(acc[mt][nt], a[mt], b[nt]);
        }

        if (kt + 2 < 8) {
            __syncthreads();                 // all warps done reading buf s
            load_chunk(kt + 2, s);
        }
    }

    // ---- Epilogue: bias + relu, float2 stores (full 32B sectors per quad) ----
    #pragma unroll
    for (int mt = 0; mt < 2; ++mt) {
        int r = m_base + warp_m * 32 + mt * 16 + gid;
        float* o0 = out + (size_t)r * N;
        float* o1 = out + (size_t)(r + 8) * N;
        #pragma unroll
        for (int nt = 0; nt < 8; ++nt) {
            int c = warp_n * 64 + nt * 8 + 2 * tg;
            float b0 = sbias[c], b1 = sbias[c + 1];
            float2 v0, v1;
            v0.x = fmaxf(acc[mt][nt][0] + b0, 0.0f);
            v0.y = fmaxf(acc[mt][nt][1] + b1, 0.0f);
            v1.x = fmaxf(acc[mt][nt][2] + b0, 0.0f);
            v1.y = fmaxf(acc[mt][nt][3] + b1, 0.0f);
            *reinterpret_cast<float2*>(o0 + c) = v0;
            *reinterpret_cast<float2*>(o1 + c) = v1;
        }
    }
}

extern "C" void kernel_launch(void* const* d_in, const int* in_sizes, int n_in,
                              void* d_out, int out_size) {
    const float* x = (const float*)d_in[0];
    const float* W = (const float*)d_in[1];
    const float* b = (const float*)d_in[2];
    float* out = (float*)d_out;

    convert_w_kernel<<<64, 256>>>(W);

    cudaFuncSetAttribute(gemm_tf32_kernel,
                         cudaFuncAttributeMaxDynamicSharedMemorySize, SMEM_TOTAL);
    gemm_tf32_kernel<<<M_TOTAL / BM, 256, SMEM_TOTAL>>>(x, b, out);
}

// round 4
// speedup vs baseline: 1.5318x; 1.5318x over previous
#include <cuda_runtime.h>
#include <cuda_fp16.h>
#include <cstdint>
#include <cstddef>

// out = relu(x[131072,256] @ W[256,256]^T + b[256]), fp32 in/out.
// fp16 mma.m16n8k16 path (same 10-bit mantissa as tf32; rel_err ~3e-4).
// W pre-converted to fp16 once. CTA tile 64(M)x128(N), K in 4 chunks of 64,
// cp.async double buffer for W, LDG+cvt+STS for x. 4 CTAs/SM (50% occ).

#define DEVI __device__ __forceinline__

static constexpr int M_TOTAL = 131072;
static constexpr int N = 256;
static constexpr int K = 256;
static constexpr int BM = 64;
static constexpr int BN = 128;
static constexpr int KC = 64;                    // K per pipeline stage
static constexpr int STRH = KC + 8;              // smem row stride in halfs (72)
static constexpr int A_STAGE = BM * STRH * 2;    // 9216 B
static constexpr int B_STAGE = BN * STRH * 2;    // 18432 B
static constexpr int STAGE   = A_STAGE + B_STAGE;
static constexpr int SM_TILES = 1024;            // [0,512) bias
static constexpr int SMEM_TOTAL = SM_TILES + 2 * STAGE;   // 56320 B

__device__ __half g_wh[N * K];                   // W pre-rounded to fp16

DEVI uint32_t smem_u32(const void* p) {
    uint32_t a;
    asm("{ .reg .u64 t; cvta.to.shared.u64 t, %1; cvt.u32.u64 %0, t; }"
        : "=r"(a) : "l"(p));
    return a;
}

DEVI void cp16(uint32_t dst, const void* src) {
    asm volatile("cp.async.cg.shared.global [%0], [%1], 16;"
                 :: "r"(dst), "l"(__cvta_generic_to_global(src)) : "memory");
}

DEVI uint32_t pack_h2(float lo, float hi) {
    uint32_t r;
    asm("cvt.rn.f16x2.f32 %0, %1, %2;" : "=r"(r) : "f"(hi), "f"(lo));
    return r;
}

DEVI void mma_f16(float* c, const uint32_t* a, const uint32_t* b) {
    asm volatile(
        "mma.sync.aligned.m16n8k16.row.col.f32.f16.f16.f32 "
        "{%0,%1,%2,%3}, {%4,%5,%6,%7}, {%8,%9}, {%0,%1,%2,%3};"
        : "+f"(c[0]), "+f"(c[1]), "+f"(c[2]), "+f"(c[3])
        : "r"(a[0]), "r"(a[1]), "r"(a[2]), "r"(a[3]), "r"(b[0]), "r"(b[1]));
}

__global__ void convert_w_kernel(const float* __restrict__ W) {
    int idx4 = (blockIdx.x * 256 + threadIdx.x) * 4;     // 16384 threads x 4
    float4 v = *reinterpret_cast<const float4*>(W + idx4);
    uint2 h;
    h.x = pack_h2(v.x, v.y);
    h.y = pack_h2(v.z, v.w);
    *reinterpret_cast<uint2*>(g_wh + idx4) = h;
}

__global__ void __launch_bounds__(256, 4)
gemm_f16_kernel(const float* __restrict__ x,
                const float* __restrict__ bias,
                float* __restrict__ out) {
    extern __shared__ char smem[];
    float* sbias = reinterpret_cast<float*>(smem);
    const uint32_t sbase = smem_u32(smem);
    const int tid  = threadIdx.x;
    const int lane = tid & 31;
    const int wid  = tid >> 5;
    const int warp_m = wid >> 2;       // 0..1  (32 rows each)
    const int warp_n = wid & 3;        // 0..3  (32 cols each)
    const int gid = lane >> 2;         // 0..7
    const int tg  = lane & 3;          // 0..3

    const int n_base = blockIdx.x * BN;        // N-split fastest -> pair co-resident
    const int m_base = blockIdx.y * BM;

    if (tid < BN) sbias[tid] = bias[n_base + tid];

    float acc[2][4][4];
    #pragma unroll
    for (int mt = 0; mt < 2; ++mt)
        #pragma unroll
        for (int nt = 0; nt < 4; ++nt)
            #pragma unroll
            for (int j = 0; j < 4; ++j)
                acc[mt][nt][j] = 0.0f;

    // ---- chunk loader: A = LDG fp32 -> cvt fp16 -> STS ; B = cp.async of g_wh ----
    auto load_chunk = [&](int kt, int s) {
        // A: 64 rows x 64 halfs; 1024 4-float granules, 4 per thread
        const float* srcA = x + (size_t)m_base * K + kt * KC;
        char* dA = smem + SM_TILES + s * STAGE;
        #pragma unroll
        for (int i = 0; i < 4; ++i) {
            int g = tid + i * 256;
            int r = g >> 4, c = g & 15;
            float4 v = *reinterpret_cast<const float4*>(srcA + (size_t)r * K + c * 4);
            uint2 h;
            h.x = pack_h2(v.x, v.y);
            h.y = pack_h2(v.z, v.w);
            *reinterpret_cast<uint2*>(dA + r * (STRH * 2) + c * 8) = h;
        }
        // B: 128 rows x 64 halfs; 1024 16B granules, 4 per thread
        const __half* srcB = g_wh + (size_t)n_base * K + kt * KC;
        uint32_t dB = sbase + SM_TILES + s * STAGE + A_STAGE;
        #pragma unroll
        for (int i = 0; i < 4; ++i) {
            int g = tid + i * 256;
            int r = g >> 3, c = g & 7;
            cp16(dB + r * (STRH * 2) + c * 16, srcB + (size_t)r * K + c * 8);
        }
        asm volatile("cp.async.commit_group;" ::: "memory");
    };

    load_chunk(0, 0);
    load_chunk(1, 1);

    #pragma unroll 1
    for (int kt = 0; kt < 4; ++kt) {
        if (kt < 3)
            asm volatile("cp.async.wait_group 1;" ::: "memory");
        else
            asm volatile("cp.async.wait_group 0;" ::: "memory");
        __syncthreads();

        const int s = kt & 1;
        // 32-bit word views (half-pair granularity): word idx = row*36 + k_half/2
        const uint32_t* Aw = reinterpret_cast<const uint32_t*>(smem + SM_TILES + s * STAGE);
        const uint32_t* Bw = reinterpret_cast<const uint32_t*>(smem + SM_TILES + s * STAGE + A_STAGE);

        #pragma unroll
        for (int ks = 0; ks < 4; ++ks) {          // k16 steps within the chunk
            const int kw = ks * 8 + tg;           // word offset of k-pair 2tg
            uint32_t a[2][4];
            #pragma unroll
            for (int mt = 0; mt < 2; ++mt) {
                int r = warp_m * 32 + mt * 16 + gid;
                a[mt][0] = Aw[r * (STRH / 2) + kw];
                a[mt][1] = Aw[(r + 8) * (STRH / 2) + kw];
                a[mt][2] = Aw[r * (STRH / 2) + kw + 4];
                a[mt][3] = Aw[(r + 8) * (STRH / 2) + kw + 4];
            }
            uint32_t b[4][2];
            #pragma unroll
            for (int nt = 0; nt < 4; ++nt) {
                int n = warp_n * 32 + nt * 8 + gid;
                b[nt][0] = Bw[n * (STRH / 2) + kw];
                b[nt][1] = Bw[n * (STRH / 2) + kw + 4];
            }
            #pragma unroll
            for (int mt = 0; mt < 2; ++mt)
                #pragma unroll
                for (int nt = 0; nt < 4; ++nt)
                    mma_f16(acc[mt][nt], a[mt], b[nt]);
        }

        if (kt + 2 < 4) {
            __syncthreads();                      // all warps done reading buf s
            load_chunk(kt + 2, s);
        }
    }

    // ---- Epilogue: bias + relu; float2 stores (quad covers 32B sector) ----
    #pragma unroll
    for (int mt = 0; mt < 2; ++mt) {
        int r0 = m_base + warp_m * 32 + mt * 16 + gid;
        float* o0 = out + (size_t)r0 * N + n_base;
        float* o1 = out + (size_t)(r0 + 8) * N + n_base;
        #pragma unroll
        for (int nt = 0; nt < 4; ++nt) {
            int c = warp_n * 32 + nt * 8 + 2 * tg;
            float b0 = sbias[c], b1 = sbias[c + 1];
            float2 v0, v1;
            v0.x = fmaxf(acc[mt][nt][0] + b0, 0.0f);
            v0.y = fmaxf(acc[mt][nt][1] + b1, 0.0f);
            v1.x = fmaxf(acc[mt][nt][2] + b0, 0.0f);
            v1.y = fmaxf(acc[mt][nt][3] + b1, 0.0f);
            *reinterpret_cast<float2*>(o0 + c) = v0;
            *reinterpret_cast<float2*>(o1 + c) = v1;
        }
    }
}

extern "C" void kernel_launch(void* const* d_in, const int* in_sizes, int n_in,
                              void* d_out, int out_size) {
    const float* x = (const float*)d_in[0];
    const float* W = (const float*)d_in[1];
    const float* b = (const float*)d_in[2];
    float* out = (float*)d_out;

    convert_w_kernel<<<64, 256>>>(W);

    cudaFuncSetAttribute(gemm_f16_kernel,
                         cudaFuncAttributeMaxDynamicSharedMemorySize, SMEM_TOTAL);
    gemm_f16_kernel<<<dim3(2, M_TOTAL / BM), 256, SMEM_TOTAL>>>(x, b, out);
}

// round 5
// speedup vs baseline: 1.5613x; 1.0193x over previous
#include <cuda_runtime.h>
#include <cuda_fp16.h>
#include <cstdint>
#include <cstddef>

// out = relu(x[131072,256] @ W[256,256]^T + b[256]), fp32 in/out.
// fp16 mma.m16n8k16, fragments via ldmatrix.x4, single-sync software pipeline.
// CTA tile 64(M)x128(N), K in 4 chunks of 64, 2-stage double buffer, 4 CTAs/SM.

#define DEVI __device__ __forceinline__

static constexpr int M_TOTAL = 131072;
static constexpr int N = 256;
static constexpr int K = 256;
static constexpr int BM = 64;
static constexpr int BN = 128;
static constexpr int KC = 64;                    // K per pipeline stage
static constexpr int STRH = 72;                  // smem row stride in halfs (144B)
static constexpr int STRB = STRH * 2;            // 144
static constexpr int A_STAGE = BM * STRB;        // 9216 B
static constexpr int B_STAGE = BN * STRB;        // 18432 B
static constexpr int STAGE   = A_STAGE + B_STAGE;
static constexpr int SM_TILES = 1024;            // [0,512) bias
static constexpr int SMEM_TOTAL = SM_TILES + 2 * STAGE;   // 56320 B
static constexpr int KTILES = K / KC;            // 4

__device__ __half g_wh[N * K];                   // W pre-rounded to fp16

DEVI uint32_t smem_u32(const void* p) {
    uint32_t a;
    asm("{ .reg .u64 t; cvta.to.shared.u64 t, %1; cvt.u32.u64 %0, t; }"
        : "=r"(a) : "l"(p));
    return a;
}

DEVI void cp16(uint32_t dst, const void* src) {
    asm volatile("cp.async.cg.shared.global [%0], [%1], 16;"
                 :: "r"(dst), "l"(__cvta_generic_to_global(src)) : "memory");
}

DEVI uint32_t pack_h2(float lo, float hi) {
    uint32_t r;
    asm("cvt.rn.f16x2.f32 %0, %1, %2;" : "=r"(r) : "f"(hi), "f"(lo));
    return r;
}

DEVI void ldm_x4(uint32_t* r, uint32_t addr) {
    asm volatile("ldmatrix.sync.aligned.m8n8.x4.shared.b16 {%0,%1,%2,%3}, [%4];"
                 : "=r"(r[0]), "=r"(r[1]), "=r"(r[2]), "=r"(r[3]) : "r"(addr));
}

DEVI void mma_f16(float* c, const uint32_t* a, const uint32_t* b) {
    asm volatile(
        "mma.sync.aligned.m16n8k16.row.col.f32.f16.f16.f32 "
        "{%0,%1,%2,%3}, {%4,%5,%6,%7}, {%8,%9}, {%0,%1,%2,%3};"
        : "+f"(c[0]), "+f"(c[1]), "+f"(c[2]), "+f"(c[3])
        : "r"(a[0]), "r"(a[1]), "r"(a[2]), "r"(a[3]), "r"(b[0]), "r"(b[1]));
}

__global__ void convert_w_kernel(const float* __restrict__ W) {
    int idx4 = (blockIdx.x * 256 + threadIdx.x) * 4;
    float4 v = *reinterpret_cast<const float4*>(W + idx4);
    uint2 h;
    h.x = pack_h2(v.x, v.y);
    h.y = pack_h2(v.z, v.w);
    *reinterpret_cast<uint2*>(g_wh + idx4) = h;
}

__global__ void __launch_bounds__(256, 4)
gemm_f16_kernel(const float* __restrict__ x,
                const float* __restrict__ bias,
                float* __restrict__ out) {
    extern __shared__ char smem[];
    float* sbias = reinterpret_cast<float*>(smem);
    const uint32_t sbase = smem_u32(smem);
    const int tid  = threadIdx.x;
    const int lane = tid & 31;
    const int wid  = tid >> 5;
    const int warp_m = wid >> 2;       // 0..1
    const int warp_n = wid & 3;        // 0..3
    const int gid = lane >> 2;
    const int tg  = lane & 3;

    const int n_base = blockIdx.x * BN;
    const int m_base = blockIdx.y * BM;

    if (tid < BN) sbias[tid] = bias[n_base + tid];

    // ldmatrix lane offsets (bytes within a stage)
    // A: lanes 0-15 -> m rows 0-15 @k0 ; lanes 16-31 -> same rows @k+8
    const uint32_t aOff = (uint32_t)((warp_m * 32 + (lane & 15)) * STRB
                                     + ((lane >> 4) * 8) * 2);
    // B: lanes 0-7 n0-7@k0, 8-15 n0-7@k8, 16-23 n8-15@k0, 24-31 n8-15@k8
    const uint32_t bOff = (uint32_t)((warp_n * 32 + (lane & 7) + ((lane >> 4) << 3)) * STRB
                                     + (((lane >> 3) & 1) * 8) * 2);

    float acc[2][4][4];
    #pragma unroll
    for (int mt = 0; mt < 2; ++mt)
        #pragma unroll
        for (int nt = 0; nt < 4; ++nt)
            #pragma unroll
            for (int j = 0; j < 4; ++j)
                acc[mt][nt][j] = 0.0f;

    auto load_chunk = [&](int kt, int s) {
        const float* srcA = x + (size_t)m_base * K + kt * KC;
        char* dA = smem + SM_TILES + s * STAGE;
        #pragma unroll
        for (int i = 0; i < 4; ++i) {
            int g = tid + i * 256;
            int r = g >> 4, c = g & 15;
            float4 v = *reinterpret_cast<const float4*>(srcA + (size_t)r * K + c * 4);
            uint2 h;
            h.x = pack_h2(v.x, v.y);
            h.y = pack_h2(v.z, v.w);
            *reinterpret_cast<uint2*>(dA + r * STRB + c * 8) = h;
        }
        const __half* srcB = g_wh + (size_t)n_base * K + kt * KC;
        uint32_t dB = sbase + SM_TILES + s * STAGE + A_STAGE;
        #pragma unroll
        for (int i = 0; i < 4; ++i) {
            int g = tid + i * 256;
            int r = g >> 3, c = g & 7;
            cp16(dB + r * STRB + c * 16, srcB + (size_t)r * K + c * 8);
        }
        asm volatile("cp.async.commit_group;" ::: "memory");
    };

    load_chunk(0, 0);

    #pragma unroll 1
    for (int kt = 0; kt < KTILES; ++kt) {
        asm volatile("cp.async.wait_group 0;" ::: "memory");
        __syncthreads();   // chunk kt ready; all reads of buf (kt+1)&1 finished

        if (kt + 1 < KTILES)
            load_chunk(kt + 1, (kt + 1) & 1);   // overlaps compute below

        const int s = kt & 1;
        const uint32_t aBase = sbase + SM_TILES + s * STAGE + aOff;
        const uint32_t bBase = sbase + SM_TILES + s * STAGE + A_STAGE + bOff;

        #pragma unroll
        for (int ks = 0; ks < 4; ++ks) {        // 4 k16 steps per chunk
            uint32_t a[2][4], b[2][4];
            ldm_x4(a[0], aBase + ks * 32);
            ldm_x4(a[1], aBase + 16 * STRB + ks * 32);
            ldm_x4(b[0], bBase + ks * 32);                 // n-tiles 0,1
            ldm_x4(b[1], bBase + 16 * STRB + ks * 32);     // n-tiles 2,3
            #pragma unroll
            for (int mt = 0; mt < 2; ++mt) {
                mma_f16(acc[mt][0], a[mt], &b[0][0]);
                mma_f16(acc[mt][1], a[mt], &b[0][2]);
                mma_f16(acc[mt][2], a[mt], &b[1][0]);
                mma_f16(acc[mt][3], a[mt], &b[1][2]);
            }
        }
    }

    // ---- Epilogue: bias + relu; float2 stores ----
    #pragma unroll
    for (int mt = 0; mt < 2; ++mt) {
        int r0 = m_base + warp_m * 32 + mt * 16 + gid;
        float* o0 = out + (size_t)r0 * N + n_base;
        float* o1 = out + (size_t)(r0 + 8) * N + n_base;
        #pragma unroll
        for (int nt = 0; nt < 4; ++nt) {
            int c = warp_n * 32 + nt * 8 + 2 * tg;
            float b0 = sbias[c], b1 = sbias[c + 1];
            float2 v0, v1;
            v0.x = fmaxf(acc[mt][nt][0] + b0, 0.0f);
            v0.y = fmaxf(acc[mt][nt][1] + b1, 0.0f);
            v1.x = fmaxf(acc[mt][nt][2] + b0, 0.0f);
            v1.y = fmaxf(acc[mt][nt][3] + b1, 0.0f);
            *reinterpret_cast<float2*>(o0 + c) = v0;
            *reinterpret_cast<float2*>(o1 + c) = v1;
        }
    }
}

extern "C" void kernel_launch(void* const* d_in, const int* in_sizes, int n_in,
                              void* d_out, int out_size) {
    const float* x = (const float*)d_in[0];
    const float* W = (const float*)d_in[1];
    const float* b = (const float*)d_in[2];
    float* out = (float*)d_out;

    convert_w_kernel<<<64, 256>>>(W);

    cudaFuncSetAttribute(gemm_f16_kernel,
                         cudaFuncAttributeMaxDynamicSharedMemorySize, SMEM_TOTAL);
    gemm_f16_kernel<<<dim3(2, M_TOTAL / BM), 256, SMEM_TOTAL>>>(x, b, out);
}

// round 6
// speedup vs baseline: 1.8605x; 1.1916x over previous
#include <cuda_runtime.h>
#include <cuda_fp16.h>
#include <cstdint>
#include <cstddef>

// out = relu(x[131072,256] @ W[256,256]^T + b[256]), fp32 in/out.
// fp16 mma.m16n8k16. CTA tile 64(M)x256(N=full), warp tile 32x64 (8 warps).
// 1.5 L1 wavefronts/MMA (was 2.0), x read once from DRAM, A-LDG latency hidden
// behind the MMA block via register staging. 2 CTAs/SM.

#define DEVI __device__ __forceinline__

static constexpr int M_TOTAL = 131072;
static constexpr int N = 256;
static constexpr int K = 256;
static constexpr int BM = 64;
static constexpr int KC = 64;                    // K per pipeline stage
static constexpr int STRB = 144;                 // smem row stride bytes (72 halfs)
static constexpr int A_STAGE = BM * STRB;        // 9216 B
static constexpr int B_STAGE = N * STRB;         // 36864 B
static constexpr int STAGE   = A_STAGE + B_STAGE;
static constexpr int SM_TILES = 1024;
static constexpr int SMEM_TOTAL = SM_TILES + 2 * STAGE;   // 93184 B
static constexpr int KTILES = K / KC;            // 4

__device__ __half g_wh[N * K];

DEVI uint32_t smem_u32(const void* p) {
    uint32_t a;
    asm("{ .reg .u64 t; cvta.to.shared.u64 t, %1; cvt.u32.u64 %0, t; }"
        : "=r"(a) : "l"(p));
    return a;
}

DEVI void cp16(uint32_t dst, const void* src) {
    asm volatile("cp.async.cg.shared.global [%0], [%1], 16;"
                 :: "r"(dst), "l"(__cvta_generic_to_global(src)) : "memory");
}

DEVI uint32_t pack_h2(float lo, float hi) {
    uint32_t r;
    asm("cvt.rn.f16x2.f32 %0, %1, %2;" : "=r"(r) : "f"(hi), "f"(lo));
    return r;
}

DEVI void ldm_x4(uint32_t* r, uint32_t addr) {
    asm volatile("ldmatrix.sync.aligned.m8n8.x4.shared.b16 {%0,%1,%2,%3}, [%4];"
                 : "=r"(r[0]), "=r"(r[1]), "=r"(r[2]), "=r"(r[3]) : "r"(addr));
}

DEVI void mma_f16(float* c, const uint32_t* a, const uint32_t* b) {
    asm volatile(
        "mma.sync.aligned.m16n8k16.row.col.f32.f16.f16.f32 "
        "{%0,%1,%2,%3}, {%4,%5,%6,%7}, {%8,%9}, {%0,%1,%2,%3};"
        : "+f"(c[0]), "+f"(c[1]), "+f"(c[2]), "+f"(c[3])
        : "r"(a[0]), "r"(a[1]), "r"(a[2]), "r"(a[3]), "r"(b[0]), "r"(b[1]));
}

__global__ void convert_w_kernel(const float* __restrict__ W) {
    int idx4 = (blockIdx.x * 256 + threadIdx.x) * 4;
    float4 v = *reinterpret_cast<const float4*>(W + idx4);
    uint2 h;
    h.x = pack_h2(v.x, v.y);
    h.y = pack_h2(v.z, v.w);
    *reinterpret_cast<uint2*>(g_wh + idx4) = h;
}

__global__ void __launch_bounds__(256, 2)
gemm_f16_kernel(const float* __restrict__ x,
                const float* __restrict__ bias,
                float* __restrict__ out) {
    extern __shared__ char smem[];
    float* sbias = reinterpret_cast<float*>(smem);
    const uint32_t sbase = smem_u32(smem);
    const int tid  = threadIdx.x;
    const int lane = tid & 31;
    const int wid  = tid >> 5;
    const int warp_m = wid >> 2;       // 0..1  (32 M rows)
    const int warp_n = wid & 3;        // 0..3  (64 N cols)
    const int gid = lane >> 2;
    const int tg  = lane & 3;

    const int m_base = blockIdx.x * BM;

    sbias[tid] = bias[tid];

    // ldmatrix lane byte offsets within a stage
    const uint32_t aOff = (uint32_t)((warp_m * 32 + (lane & 15)) * STRB
                                     + ((lane >> 4) * 8) * 2);
    const uint32_t bOff = (uint32_t)((warp_n * 64 + (lane & 7) + ((lane >> 4) << 3)) * STRB
                                     + (((lane >> 3) & 1) * 8) * 2);

    float acc[2][8][4];
    #pragma unroll
    for (int mt = 0; mt < 2; ++mt)
        #pragma unroll
        for (int nt = 0; nt < 8; ++nt)
            #pragma unroll
            for (int j = 0; j < 4; ++j)
                acc[mt][nt][j] = 0.0f;

    // A loader indices: 1024 8B-granules; 4 per thread
    const int ar = tid >> 4;           // row 0..15 (+16 per i)
    const int ac = tid & 15;           // 16B src granule / 8B dst granule
    // B loader: 2048 16B granules; 8 per thread
    const int br = tid >> 3;           // row 0..31 (+32 per i)
    const int bc = tid & 7;

    auto load_B = [&](int kt, int s) {
        const __half* srcB = g_wh + kt * KC;
        uint32_t dB = sbase + SM_TILES + s * STAGE + A_STAGE;
        #pragma unroll
        for (int i = 0; i < 8; ++i) {
            int r = br + i * 32;
            cp16(dB + r * STRB + bc * 16, srcB + (size_t)r * K + bc * 8);
        }
        asm volatile("cp.async.commit_group;" ::: "memory");
    };

    auto ldg_A = [&](int kt, float4* pf) {
        const float* srcA = x + (size_t)m_base * K + kt * KC;
        #pragma unroll
        for (int i = 0; i < 4; ++i)
            pf[i] = *reinterpret_cast<const float4*>(srcA + (size_t)(ar + i * 16) * K + ac * 4);
    };

    auto sts_A = [&](int s, const float4* pf) {
        char* dA = smem + SM_TILES + s * STAGE;
        #pragma unroll
        for (int i = 0; i < 4; ++i) {
            uint2 h;
            h.x = pack_h2(pf[i].x, pf[i].y);
            h.y = pack_h2(pf[i].z, pf[i].w);
            *reinterpret_cast<uint2*>(dA + (ar + i * 16) * STRB + ac * 8) = h;
        }
    };

    // Prologue: chunk 0 fully staged
    {
        float4 pf[4];
        ldg_A(0, pf);
        load_B(0, 0);
        sts_A(0, pf);
    }

    #pragma unroll 1
    for (int kt = 0; kt < KTILES; ++kt) {
        asm volatile("cp.async.wait_group 0;" ::: "memory");
        __syncthreads();   // chunk kt ready; all reads of the other buffer done

        const bool pre = (kt + 1 < KTILES);
        float4 pf[4];
        if (pre) {
            ldg_A(kt + 1, pf);             // LDGs in flight during MMA block
            load_B(kt + 1, (kt + 1) & 1);  // cp.async, non-blocking
        }

        const int s = kt & 1;
        const uint32_t aBase = sbase + SM_TILES + s * STAGE + aOff;
        const uint32_t bBase = sbase + SM_TILES + s * STAGE + A_STAGE + bOff;

        #pragma unroll
        for (int ks = 0; ks < 4; ++ks) {
            uint32_t a[2][4], b[4][4];
            ldm_x4(a[0], aBase + ks * 32);
            ldm_x4(a[1], aBase + 16 * STRB + ks * 32);
            #pragma unroll
            for (int j = 0; j < 4; ++j)
                ldm_x4(b[j], bBase + (16 * j) * STRB + ks * 32);
            #pragma unroll
            for (int mt = 0; mt < 2; ++mt)
                #pragma unroll
                for (int nt = 0; nt < 8; ++nt)
                    mma_f16(acc[mt][nt], a[mt], &b[nt >> 1][(nt & 1) * 2]);
        }

        if (pre)
            sts_A((kt + 1) & 1, pf);       // LDG latency already absorbed
    }

    // ---- Epilogue: bias + relu; float2 stores ----
    #pragma unroll
    for (int mt = 0; mt < 2; ++mt) {
        int r0 = m_base + warp_m * 32 + mt * 16 + gid;
        float* o0 = out + (size_t)r0 * N;
        float* o1 = out + (size_t)(r0 + 8) * N;
        #pragma unroll
        for (int nt = 0; nt < 8; ++nt) {
            int c = warp_n * 64 + nt * 8 + 2 * tg;
            float b0 = sbias[c], b1 = sbias[c + 1];
            float2 v0, v1;
            v0.x = fmaxf(acc[mt][nt][0] + b0, 0.0f);
            v0.y = fmaxf(acc[mt][nt][1] + b1, 0.0f);
            v1.x = fmaxf(acc[mt][nt][2] + b0, 0.0f);
            v1.y = fmaxf(acc[mt][nt][3] + b1, 0.0f);
            *reinterpret_cast<float2*>(o0 + c) = v0;
            *reinterpret_cast<float2*>(o1 + c) = v1;
        }
    }
}

extern "C" void kernel_launch(void* const* d_in, const int* in_sizes, int n_in,
                              void* d_out, int out_size) {
    const float* x = (const float*)d_in[0];
    const float* W = (const float*)d_in[1];
    const float* b = (const float*)d_in[2];
    float* out = (float*)d_out;

    convert_w_kernel<<<64, 256>>>(W);

    cudaFuncSetAttribute(gemm_f16_kernel,
                         cudaFuncAttributeMaxDynamicSharedMemorySize, SMEM_TOTAL);
    gemm_f16_kernel<<<M_TOTAL / BM, 256, SMEM_TOTAL>>>(x, b, out);
}

// round 7
// speedup vs baseline: 1.9131x; 1.0283x over previous
#include <cuda_runtime.h>
#include <cuda_fp16.h>
#include <cstdint>
#include <cstddef>

// out = relu(x[131072,256] @ W[256,256]^T + b[256]), fp32 in/out.
// fp16 mma.m16n8k16. CTA 64x256, warp tile 32x64, 8 warps, 2 CTAs/SM.
// Register-level fragment double-buffer over ks; LDG hoisted above barrier;
// cp.async B issued right after sync.

#define DEVI __device__ __forceinline__

static constexpr int M_TOTAL = 131072;
static constexpr int N = 256;
static constexpr int K = 256;
static constexpr int BM = 64;
static constexpr int KC = 64;
static constexpr int STRB = 144;                 // smem row stride bytes
static constexpr int A_STAGE = BM * STRB;        // 9216 B
static constexpr int B_STAGE = N * STRB;         // 36864 B
static constexpr int STAGE   = A_STAGE + B_STAGE;
static constexpr int SM_TILES = 1024;
static constexpr int SMEM_TOTAL = SM_TILES + 2 * STAGE;   // 93184 B
static constexpr int KTILES = K / KC;            // 4

__device__ __half g_wh[N * K];

DEVI uint32_t smem_u32(const void* p) {
    uint32_t a;
    asm("{ .reg .u64 t; cvta.to.shared.u64 t, %1; cvt.u32.u64 %0, t; }"
        : "=r"(a) : "l"(p));
    return a;
}

DEVI void cp16(uint32_t dst, const void* src) {
    asm volatile("cp.async.cg.shared.global [%0], [%1], 16;"
                 :: "r"(dst), "l"(__cvta_generic_to_global(src)) : "memory");
}

DEVI uint32_t pack_h2(float lo, float hi) {
    uint32_t r;
    asm("cvt.rn.f16x2.f32 %0, %1, %2;" : "=r"(r) : "f"(hi), "f"(lo));
    return r;
}

DEVI void ldm_x4(uint32_t* r, uint32_t addr) {
    asm volatile("ldmatrix.sync.aligned.m8n8.x4.shared.b16 {%0,%1,%2,%3}, [%4];"
                 : "=r"(r[0]), "=r"(r[1]), "=r"(r[2]), "=r"(r[3]) : "r"(addr));
}

DEVI void mma_f16(float* c, const uint32_t* a, const uint32_t* b) {
    asm volatile(
        "mma.sync.aligned.m16n8k16.row.col.f32.f16.f16.f32 "
        "{%0,%1,%2,%3}, {%4,%5,%6,%7}, {%8,%9}, {%0,%1,%2,%3};"
        : "+f"(c[0]), "+f"(c[1]), "+f"(c[2]), "+f"(c[3])
        : "r"(a[0]), "r"(a[1]), "r"(a[2]), "r"(a[3]), "r"(b[0]), "r"(b[1]));
}

__global__ void convert_w_kernel(const float* __restrict__ W) {
    int idx4 = (blockIdx.x * 256 + threadIdx.x) * 4;
    float4 v = *reinterpret_cast<const float4*>(W + idx4);
    uint2 h;
    h.x = pack_h2(v.x, v.y);
    h.y = pack_h2(v.z, v.w);
    *reinterpret_cast<uint2*>(g_wh + idx4) = h;
}

__global__ void __launch_bounds__(256, 2)
gemm_f16_kernel(const float* __restrict__ x,
                const float* __restrict__ bias,
                float* __restrict__ out) {
    extern __shared__ char smem[];
    float* sbias = reinterpret_cast<float*>(smem);
    const uint32_t sbase = smem_u32(smem);
    const int tid  = threadIdx.x;
    const int lane = tid & 31;
    const int wid  = tid >> 5;
    const int warp_m = wid >> 2;
    const int warp_n = wid & 3;
    const int gid = lane >> 2;
    const int tg  = lane & 3;

    const int m_base = blockIdx.x * BM;

    sbias[tid] = bias[tid];

    const uint32_t aOff = (uint32_t)((warp_m * 32 + (lane & 15)) * STRB
                                     + ((lane >> 4) * 8) * 2);
    const uint32_t bOff = (uint32_t)((warp_n * 64 + (lane & 7) + ((lane >> 4) << 3)) * STRB
                                     + (((lane >> 3) & 1) * 8) * 2);

    float acc[2][8][4];
    #pragma unroll
    for (int mt = 0; mt < 2; ++mt)
        #pragma unroll
        for (int nt = 0; nt < 8; ++nt)
            #pragma unroll
            for (int j = 0; j < 4; ++j)
                acc[mt][nt][j] = 0.0f;

    const int ar = tid >> 4;
    const int ac = tid & 15;
    const int br = tid >> 3;
    const int bc = tid & 7;

    auto load_B = [&](int kt, int s) {
        const __half* srcB = g_wh + kt * KC;
        uint32_t dB = sbase + SM_TILES + s * STAGE + A_STAGE;
        #pragma unroll
        for (int i = 0; i < 8; ++i) {
            int r = br + i * 32;
            cp16(dB + r * STRB + bc * 16, srcB + (size_t)r * K + bc * 8);
        }
        asm volatile("cp.async.commit_group;" ::: "memory");
    };

    auto ldg_A = [&](int kt, float4* pf) {
        const float* srcA = x + (size_t)m_base * K + kt * KC;
        #pragma unroll
        for (int i = 0; i < 4; ++i)
            pf[i] = *reinterpret_cast<const float4*>(srcA + (size_t)(ar + i * 16) * K + ac * 4);
    };

    auto sts_A = [&](int s, const float4* pf) {
        char* dA = smem + SM_TILES + s * STAGE;
        #pragma unroll
        for (int i = 0; i < 4; ++i) {
            uint2 h;
            h.x = pack_h2(pf[i].x, pf[i].y);
            h.y = pack_h2(pf[i].z, pf[i].w);
            *reinterpret_cast<uint2*>(dA + (ar + i * 16) * STRB + ac * 8) = h;
        }
    };

    // Prologue
    {
        float4 pf[4];
        ldg_A(0, pf);
        load_B(0, 0);
        sts_A(0, pf);
    }

    #pragma unroll 1
    for (int kt = 0; kt < KTILES; ++kt) {
        const bool pre = (kt + 1 < KTILES);
        float4 pf[4];
        if (pre) ldg_A(kt + 1, pf);        // LDG latency spans barrier + MMAs

        asm volatile("cp.async.wait_group 0;" ::: "memory");
        __syncthreads();                   // chunk kt ready; other buffer free

        if (pre) load_B(kt + 1, (kt + 1) & 1);

        const int s = kt & 1;
        const uint32_t aBase = sbase + SM_TILES + s * STAGE + aOff;
        const uint32_t bBase = sbase + SM_TILES + s * STAGE + A_STAGE + bOff;

        // register-level fragment double buffer over the 4 k16 steps
        uint32_t a[2][2][4], b[2][4][4];
        ldm_x4(a[0][0], aBase);
        ldm_x4(a[0][1], aBase + 16 * STRB);
        #pragma unroll
        for (int j = 0; j < 4; ++j)
            ldm_x4(b[0][j], bBase + (16 * j) * STRB);

        #pragma unroll
        for (int ks = 0; ks < 4; ++ks) {
            const int cur = ks & 1, nxt = cur ^ 1;
            if (ks < 3) {
                ldm_x4(a[nxt][0], aBase + (ks + 1) * 32);
                ldm_x4(a[nxt][1], aBase + 16 * STRB + (ks + 1) * 32);
                #pragma unroll
                for (int j = 0; j < 4; ++j)
                    ldm_x4(b[nxt][j], bBase + (16 * j) * STRB + (ks + 1) * 32);
            }
            #pragma unroll
            for (int mt = 0; mt < 2; ++mt)
                #pragma unroll
                for (int nt = 0; nt < 8; ++nt)
                    mma_f16(acc[mt][nt], a[cur][mt], &b[cur][nt >> 1][(nt & 1) * 2]);
        }

        if (pre) sts_A((kt + 1) & 1, pf);  // LDG data long since landed
    }

    // ---- Epilogue: bias + relu; float2 stores ----
    #pragma unroll
    for (int mt = 0; mt < 2; ++mt) {
        int r0 = m_base + warp_m * 32 + mt * 16 + gid;
        float* o0 = out + (size_t)r0 * N;
        float* o1 = out + (size_t)(r0 + 8) * N;
        #pragma unroll
        for (int nt = 0; nt < 8; ++nt) {
            int c = warp_n * 64 + nt * 8 + 2 * tg;
            float b0 = sbias[c], b1 = sbias[c + 1];
            float2 v0, v1;
            v0.x = fmaxf(acc[mt][nt][0] + b0, 0.0f);
            v0.y = fmaxf(acc[mt][nt][1] + b1, 0.0f);
            v1.x = fmaxf(acc[mt][nt][2] + b0, 0.0f);
            v1.y = fmaxf(acc[mt][nt][3] + b1, 0.0f);
            *reinterpret_cast<float2*>(o0 + c) = v0;
            *reinterpret_cast<float2*>(o1 + c) = v1;
        }
    }
}

extern "C" void kernel_launch(void* const* d_in, const int* in_sizes, int n_in,
                              void* d_out, int out_size) {
    const float* x = (const float*)d_in[0];
    const float* W = (const float*)d_in[1];
    const float* b = (const float*)d_in[2];
    float* out = (float*)d_out;

    convert_w_kernel<<<64, 256>>>(W);

    cudaFuncSetAttribute(gemm_f16_kernel,
                         cudaFuncAttributeMaxDynamicSharedMemorySize, SMEM_TOTAL);
    gemm_f16_kernel<<<M_TOTAL / BM, 256, SMEM_TOTAL>>>(x, b, out);
}